// round 2
// baseline (speedup 1.0000x reference)
#include <cuda_runtime.h>
#include <cstdint>

#define TT   8
#define NN   20000
#define EE   640000
#define ETOT (EE + NN)   // edges + self loops
#define HID  32

// ---------------- static device scratch ----------------
__device__ int   g_count[NN];
__device__ int   g_off[NN + 1];
__device__ int   g_cursor[NN];
__device__ int   g_srclist[ETOT];
__device__ float g_h2[NN * HID];
__device__ float g_as2[NN];
__device__ float g_ad2[NN];
__device__ float g_h[NN * HID];     // GRU hidden state
__device__ float g_A1[4];           // As1[0..1], Ad1[0..1]

// ---------------- setup: zero state + fold layer-1 attention vectors ----------------
__global__ void k_setup(const float* __restrict__ W1,
                        const float* __restrict__ as1,
                        const float* __restrict__ ad1) {
    int i = blockIdx.x * blockDim.x + threadIdx.x;
    int stride = gridDim.x * blockDim.x;
    for (int j = i; j < NN * HID; j += stride) g_h[j] = 0.0f;
    for (int j = i; j < NN; j += stride) g_count[j] = 0;
    if (blockIdx.x == 0 && threadIdx.x < 4) {
        int h = threadIdx.x & 1;
        const float* a = (threadIdx.x >= 2) ? ad1 : as1;
        float s = 0.0f;
        for (int c = 0; c < HID; c++) s += W1[h * HID + c] * a[h * HID + c];
        g_A1[threadIdx.x] = s;
    }
}

// ---------------- CSR build ----------------
__global__ void k_count(const int* __restrict__ ei) {
    int i = blockIdx.x * blockDim.x + threadIdx.x;
    if (i >= ETOT) return;
    int dst = (i < EE) ? ei[EE + i] : (i - EE);
    atomicAdd(&g_count[dst], 1);
}

__global__ void k_scan() {
    __shared__ int partial[1024];
    const int CH = (NN + 1023) / 1024;   // 20
    int tid = threadIdx.x;
    int base = tid * CH;
    int s = 0;
    for (int j = 0; j < CH; j++) {
        int idx = base + j;
        if (idx < NN) s += g_count[idx];
    }
    partial[tid] = s;
    __syncthreads();
    for (int off = 1; off < 1024; off <<= 1) {
        int v = 0;
        if (tid >= off) v = partial[tid - off];
        __syncthreads();
        if (tid >= off) partial[tid] += v;
        __syncthreads();
    }
    int run = (tid == 0) ? 0 : partial[tid - 1];
    for (int j = 0; j < CH; j++) {
        int idx = base + j;
        if (idx < NN) {
            int c = g_count[idx];
            g_off[idx] = run;
            g_cursor[idx] = run;
            g_count[idx] = 0;     // ready for next timestep
            run += c;
        }
    }
    if (tid == 1023) g_off[NN] = partial[1023];
}

__global__ void k_scatter(const int* __restrict__ ei) {
    int i = blockIdx.x * blockDim.x + threadIdx.x;
    if (i >= ETOT) return;
    int src, dst;
    if (i < EE) { src = ei[i]; dst = ei[EE + i]; }
    else        { src = dst = i - EE; }
    int pos = atomicAdd(&g_cursor[dst], 1);
    g_srclist[pos] = src;
}

// ---------------- layer 1 (scalar attention) + projection to h2 / layer-2 logits ----------------
__global__ void k_layer1(const float* __restrict__ xt,
                         const float* __restrict__ W1,
                         const float* __restrict__ b1,
                         const float* __restrict__ W2,
                         const float* __restrict__ as2w,
                         const float* __restrict__ ad2w) {
    __shared__ float sW1[64], sB1[64], sW2[64 * 32], sAs2[32], sAd2[32];
    int tid = threadIdx.x;
    for (int j = tid; j < 64; j += blockDim.x) { sW1[j] = W1[j]; sB1[j] = b1[j]; }
    for (int j = tid; j < 2048; j += blockDim.x) sW2[j] = W2[j];
    for (int j = tid; j < 32; j += blockDim.x) { sAs2[j] = as2w[j]; sAd2[j] = ad2w[j]; }
    __syncthreads();

    int n = blockIdx.x * blockDim.x + tid;
    if (n >= NN) return;

    float As10 = g_A1[0], As11 = g_A1[1], Ad10 = g_A1[2], Ad11 = g_A1[3];
    float xd = xt[n];
    int beg = g_off[n], end = g_off[n + 1];

    float den0 = 0.f, den1 = 0.f, num0 = 0.f, num1 = 0.f;
    for (int e = beg; e < end; e++) {
        int s = g_srclist[e];
        float xs = __ldg(&xt[s]);
        float r0 = xs * As10 + xd * Ad10; r0 = (r0 > 0.f) ? r0 : 0.2f * r0;
        float w0 = __expf(r0); den0 += w0; num0 += w0 * xs;
        float r1 = xs * As11 + xd * Ad11; r1 = (r1 > 0.f) ? r1 : 0.2f * r1;
        float w1 = __expf(r1); den1 += w1; num1 += w1 * xs;
    }
    float S0 = num0 / (den0 + 1e-16f);
    float S1 = num1 / (den1 + 1e-16f);

    float z1[64];
#pragma unroll
    for (int k = 0; k < 64; k++) {
        float v = ((k < 32) ? S0 : S1) * sW1[k] + sB1[k];
        z1[k] = (v > 0.f) ? v : (__expf(v) - 1.0f);
    }

    float as2v = 0.f, ad2v = 0.f;
    float4* dst4 = (float4*)&g_h2[(size_t)n * HID];
    for (int c4 = 0; c4 < 8; c4++) {
        float a0 = 0.f, a1 = 0.f, a2 = 0.f, a3 = 0.f;
#pragma unroll
        for (int k = 0; k < 64; k++) {
            float z = z1[k];
            const float* w = &sW2[k * 32 + c4 * 4];
            a0 += z * w[0]; a1 += z * w[1]; a2 += z * w[2]; a3 += z * w[3];
        }
        int cb = c4 * 4;
        as2v += a0 * sAs2[cb] + a1 * sAs2[cb + 1] + a2 * sAs2[cb + 2] + a3 * sAs2[cb + 3];
        ad2v += a0 * sAd2[cb] + a1 * sAd2[cb + 1] + a2 * sAd2[cb + 2] + a3 * sAd2[cb + 3];
        dst4[c4] = make_float4(a0, a1, a2, a3);
    }
    g_as2[n] = as2v;
    g_ad2[n] = ad2v;
}

// ---------------- layer 2 gather (warp per dst node) + fused GRU cell ----------------
__global__ void k_layer2(const float* __restrict__ b2,
                         const float* __restrict__ Wih,
                         const float* __restrict__ Whh,
                         const float* __restrict__ bih,
                         const float* __restrict__ bhh) {
    __shared__ float sWih[96 * 33];
    __shared__ float sWhh[96 * 33];
    __shared__ float sbih[96], sbhh[96], sb2[32];
    int tid = threadIdx.x;
    for (int j = tid; j < 96 * 32; j += blockDim.x) {
        int r = j >> 5, k = j & 31;
        sWih[r * 33 + k] = Wih[j];
        sWhh[r * 33 + k] = Whh[j];
    }
    for (int j = tid; j < 96; j += blockDim.x) { sbih[j] = bih[j]; sbhh[j] = bhh[j]; }
    for (int j = tid; j < 32; j += blockDim.x) sb2[j] = b2[j];
    __syncthreads();

    int warp = tid >> 5, lane = tid & 31;
    int n = blockIdx.x * (blockDim.x >> 5) + warp;
    if (n >= NN) return;

    float ad2v = g_ad2[n];
    int beg = g_off[n], end = g_off[n + 1];
    float acc = 0.f, den = 0.f;
    for (int e = beg; e < end; e++) {
        int s = g_srclist[e];                 // warp-uniform broadcast load
        float raw = g_as2[s] + ad2v;
        raw = (raw > 0.f) ? raw : 0.2f * raw;
        float w = __expf(raw);
        den += w;
        acc += w * g_h2[(size_t)s * HID + lane];   // coalesced 128B row
    }
    float o = acc / (den + 1e-16f) + sb2[lane];
    float z2 = (o > 0.f) ? o : (__expf(o) - 1.0f);
    float hv = g_h[(size_t)n * HID + lane];

    float ri = 0.f, zi = 0.f, ni = 0.f, rh = 0.f, zh = 0.f, nh = 0.f;
#pragma unroll
    for (int k = 0; k < 32; k++) {
        float zk = __shfl_sync(0xffffffffu, z2, k);
        float hk = __shfl_sync(0xffffffffu, hv, k);
        ri += zk * sWih[lane * 33 + k];
        zi += zk * sWih[(32 + lane) * 33 + k];
        ni += zk * sWih[(64 + lane) * 33 + k];
        rh += hk * sWhh[lane * 33 + k];
        zh += hk * sWhh[(32 + lane) * 33 + k];
        nh += hk * sWhh[(64 + lane) * 33 + k];
    }
    float r = 1.0f / (1.0f + __expf(-(ri + sbih[lane] + rh + sbhh[lane])));
    float z = 1.0f / (1.0f + __expf(-(zi + sbih[32 + lane] + zh + sbhh[32 + lane])));
    float ng = tanhf(ni + sbih[64 + lane] + r * (nh + sbhh[64 + lane]));
    g_h[(size_t)n * HID + lane] = (1.0f - z) * ng + z * hv;
}

// ---------------- output projection ----------------
__global__ void k_out(const float* __restrict__ Wout,
                      const float* __restrict__ bout,
                      float* __restrict__ out) {
    int tid = threadIdx.x;
    int warp = tid >> 5, lane = tid & 31;
    int n = blockIdx.x * (blockDim.x >> 5) + warp;
    if (n >= NN) return;
    float v = g_h[(size_t)n * HID + lane] * __ldg(&Wout[lane]);
#pragma unroll
    for (int o = 16; o; o >>= 1) v += __shfl_xor_sync(0xffffffffu, v, o);
    if (lane == 0) out[n] = v + bout[0];
}

// ---------------- launcher ----------------
extern "C" void kernel_launch(void* const* d_in, const int* in_sizes, int n_in,
                              void* d_out, int out_size) {
    const float* x    = (const float*)d_in[0];
    const int*   ei   = (const int*)  d_in[1];
    const float* W1   = (const float*)d_in[2];
    const float* as1  = (const float*)d_in[3];
    const float* ad1  = (const float*)d_in[4];
    const float* b1   = (const float*)d_in[5];
    const float* W2   = (const float*)d_in[6];
    const float* as2  = (const float*)d_in[7];
    const float* ad2  = (const float*)d_in[8];
    const float* b2   = (const float*)d_in[9];
    const float* Wih  = (const float*)d_in[10];
    const float* Whh  = (const float*)d_in[11];
    const float* bih  = (const float*)d_in[12];
    const float* bhh  = (const float*)d_in[13];
    const float* Wout = (const float*)d_in[14];
    const float* bout = (const float*)d_in[15];
    float* out = (float*)d_out;

    const int EB = (ETOT + 255) / 256;

    k_setup<<<160, 256>>>(W1, as1, ad1);
    for (int t = 0; t < TT; t++) {
        const int*   eit = ei + (size_t)t * 2 * EE;
        const float* xt  = x  + (size_t)t * NN;
        k_count<<<EB, 256>>>(eit);
        k_scan<<<1, 1024>>>();
        k_scatter<<<EB, 256>>>(eit);
        k_layer1<<<(NN + 127) / 128, 128>>>(xt, W1, b1, W2, as2, ad2);
        k_layer2<<<(NN + 7) / 8, 256>>>(b2, Wih, Whh, bih, bhh);
    }
    k_out<<<(NN + 7) / 8, 256>>>(Wout, bout, out);
}